// round 7
// baseline (speedup 1.0000x reference)
#include <cuda_runtime.h>

#define LOG_SQRT_2PI 0.9189385332046727f
#define PRIOR_BLOCKS 32

// Per-block partial sums of the prior, written by prior_kernel,
// folded by every mse warp's epilogue (one L2/L1-resident 128B line).
__device__ float g_prior_partials[PRIOR_BLOCKS];

// ---------------------------------------------------------------------------
// Kernel A: parallel prior partial sums.
// 32 blocks x 256 threads = 8192 threads -> 1 row/thread at B=8192.
// ---------------------------------------------------------------------------
__global__ void prior_kernel(const float* __restrict__ pred,
                             const float* __restrict__ sigma,
                             int B) {
    float acc = 0.0f;
    int nthreads = gridDim.x * blockDim.x;
    for (int row = blockIdx.x * blockDim.x + threadIdx.x; row < B; row += nthreads) {
        const float* p = pred + (size_t)row * 7;
        float O2  = p[0], N2 = p[1], H2 = p[2], CO2 = p[3];
        float H2O = p[4], CH4 = p[5], NH3 = p[6];

        float H = 2.0f*H2 + 2.0f*H2O + 3.0f*NH3 + 4.0f*CH4;
        float C = CO2 + CH4;
        float O = 2.0f*O2 + 2.0f*CO2 + H2O;
        float N = 2.0f*N2 + NH3;

        float mu0=0.f, mu1=0.f, mu2=0.f, mu3=0.f, mu4=0.f, mu5=0.f, mu6=0.f;

        bool condA = (H > 2.0f*O + 4.0f*C);
        if (condA) {
            if (3.0f*N < H - 2.0f*O - 4.0f*C) {
                // branch A1: D = H - N - 2C
                float inv = 1.0f / (H - N - 2.0f*C);
                mu2 = (H - 2.0f*O - 4.0f*C - 3.0f*N) * inv;
                mu4 = 2.0f*O * inv;
                mu5 = 2.0f*C * inv;
                mu6 = 2.0f*N * inv;
            } else {
                // branch A2: D = H + 2C + 3N + 4O
                float inv = 1.0f / (H + 2.0f*C + 3.0f*N + 4.0f*O);
                mu1 = (3.0f*N + 4.0f*C + 2.0f*O - H) * inv;
                mu4 = 6.0f*O * inv;
                mu5 = 6.0f*C * inv;
                mu6 = (2.0f*H - 8.0f*C - 4.0f*O) * inv;
            }
        } else if (2.0f*O > H + 4.0f*C) {
            // branch B: D = H + 2O + 2N
            float inv = 1.0f / (H + 2.0f*O + 2.0f*N);
            mu0 = (2.0f*O - H - 4.0f*C) * inv;
            mu1 = 2.0f*N * inv;
            mu3 = 4.0f*C * inv;
            mu4 = 2.0f*H * inv;
        } else if (fabsf(H + C + O + N - 1.0f) < 1e-3f) {
            // branch C: D1 = H + 2O + 2N, D2 = 2H + 4O + 4N
            float inv1 = 1.0f / (H + 2.0f*O + 2.0f*N);
            float inv2 = 1.0f / (2.0f*H + 4.0f*O + 4.0f*N);
            mu1 = 2.0f*N * inv1;
            mu3 = (2.0f*O + 4.0f*C - H) * inv2;
            mu4 = (H + 2.0f*O - 4.0f*C) * inv1;
            mu5 = (H - 2.0f*O + 4.0f*C) * inv2;
        }
        // else: unclassified -> mu = 0

        const float* s = sigma + (size_t)row * 7;
        float mu[7] = {mu0, mu1, mu2, mu3, mu4, mu5, mu6};
        #pragma unroll
        for (int i = 0; i < 7; i++) {
            float sg = s[i];
            float d  = p[i] - mu[i];
            acc += LOG_SQRT_2PI + __logf(sg) + d*d / (2.0f * sg * sg);
        }
    }

    // Block reduction: warp shuffle -> smem -> warp shuffle
    __shared__ float warp_sums[8];
    #pragma unroll
    for (int off = 16; off; off >>= 1)
        acc += __shfl_down_sync(0xffffffffu, acc, off);
    int lane = threadIdx.x & 31;
    int wid  = threadIdx.x >> 5;
    if (lane == 0) warp_sums[wid] = acc;
    __syncthreads();
    if (wid == 0) {
        int nwarps = blockDim.x >> 5;
        acc = (lane < nwarps) ? warp_sums[lane] : 0.0f;
        #pragma unroll
        for (int off = 16; off; off >>= 1)
            acc += __shfl_down_sync(0xffffffffu, acc, off);
        if (lane == 0) g_prior_partials[blockIdx.x] = acc;
    }
}

// ---------------------------------------------------------------------------
// Kernel B: WARP-per-row streaming MSE. 8 warps/block, 1024 blocks at B=8192.
// No smem, no __syncthreads. Each warp walks its 16KB row from both inputs
// with 8 independent LDG.128 in flight per iteration. The prior fold rides
// the same 5-step shuffle tree as the MSE reduction:
//   out[row] = sum_lane( acc_lane * scale + prior_partial[lane] * invB )
// ---------------------------------------------------------------------------
__global__ void mse_posterior_kernel(const float4* __restrict__ yR,
                                     const float4* __restrict__ yS,
                                     float* __restrict__ out,
                                     int B,
                                     int Sv,        // S / 4 (# of float4 per row)
                                     float scale,   // 50 / S
                                     float invB) {  // 1 / B
    int lane = threadIdx.x & 31;
    int row  = blockIdx.x * (blockDim.x >> 5) + (threadIdx.x >> 5);
    if (row >= B) return;

    const float4* r = yR + (size_t)row * Sv;
    const float4* s = yS + (size_t)row * Sv;

    float acc = 0.0f;
    if ((Sv & 127) == 0) {
        // Sv multiple of 128: 4 float4 per lane per iteration, Sv/128 iters.
        float p0 = 0.f, p1 = 0.f, p2 = 0.f, p3 = 0.f;
        int iters = Sv >> 7;                    // Sv / 128
        #pragma unroll 4
        for (int j = 0; j < iters; j++) {
            int base = (j << 7) + lane;         // j*128 + lane
            float4 a0 = __ldg(&r[base]);
            float4 a1 = __ldg(&r[base + 32]);
            float4 a2 = __ldg(&r[base + 64]);
            float4 a3 = __ldg(&r[base + 96]);
            float4 b0 = __ldg(&s[base]);
            float4 b1 = __ldg(&s[base + 32]);
            float4 b2 = __ldg(&s[base + 64]);
            float4 b3 = __ldg(&s[base + 96]);
            float d;
            d = a0.x-b0.x; p0 = fmaf(d,d,p0);  d = a0.y-b0.y; p0 = fmaf(d,d,p0);
            d = a0.z-b0.z; p0 = fmaf(d,d,p0);  d = a0.w-b0.w; p0 = fmaf(d,d,p0);
            d = a1.x-b1.x; p1 = fmaf(d,d,p1);  d = a1.y-b1.y; p1 = fmaf(d,d,p1);
            d = a1.z-b1.z; p1 = fmaf(d,d,p1);  d = a1.w-b1.w; p1 = fmaf(d,d,p1);
            d = a2.x-b2.x; p2 = fmaf(d,d,p2);  d = a2.y-b2.y; p2 = fmaf(d,d,p2);
            d = a2.z-b2.z; p2 = fmaf(d,d,p2);  d = a2.w-b2.w; p2 = fmaf(d,d,p2);
            d = a3.x-b3.x; p3 = fmaf(d,d,p3);  d = a3.y-b3.y; p3 = fmaf(d,d,p3);
            d = a3.z-b3.z; p3 = fmaf(d,d,p3);  d = a3.w-b3.w; p3 = fmaf(d,d,p3);
        }
        acc = (p0 + p1) + (p2 + p3);
    } else {
        // Generic fallback: simple per-lane stride-32 loop.
        for (int i = lane; i < Sv; i += 32) {
            float4 a = __ldg(&r[i]);
            float4 b = __ldg(&s[i]);
            float d;
            d = a.x-b.x; acc = fmaf(d,d,acc);  d = a.y-b.y; acc = fmaf(d,d,acc);
            d = a.z-b.z; acc = fmaf(d,d,acc);  d = a.w-b.w; acc = fmaf(d,d,acc);
        }
    }

    // Merged epilogue: MSE term + prior fold in ONE shuffle tree.
    // PRIOR_BLOCKS == 32 == warp size: lane i carries partial i.
    float v = acc * scale + g_prior_partials[lane] * invB;
    #pragma unroll
    for (int off = 16; off; off >>= 1)
        v += __shfl_down_sync(0xffffffffu, v, off);
    if (lane == 0) out[row] = v;
}

extern "C" void kernel_launch(void* const* d_in, const int* in_sizes, int n_in,
                              void* d_out, int out_size) {
    const float* pred  = (const float*)d_in[0];   // [B,7]
    const float* sigma = (const float*)d_in[1];   // [B,7]
    const float* yR    = (const float*)d_in[2];   // [B,S]
    const float* yS    = (const float*)d_in[3];   // [B,S]
    float* out = (float*)d_out;                   // [B]

    int B = in_sizes[0] / 7;
    int S = in_sizes[2] / B;
    int Sv = S / 4;                               // S=4096 -> 1024 float4/row
    float scale = 50.0f / (float)S;               // likelihood scale
    float invB  = 1.0f / (float)B;

    prior_kernel<<<PRIOR_BLOCKS, 256>>>(pred, sigma, B);

    int warps_per_block = 8;                      // 256 threads
    int blocks = (B + warps_per_block - 1) / warps_per_block;
    mse_posterior_kernel<<<blocks, 256>>>((const float4*)yR, (const float4*)yS,
                                          out, B, Sv, scale, invB);
}